// round 2
// baseline (speedup 1.0000x reference)
#include <cuda_runtime.h>
#include <cstdint>

// Problem constants (fixed by setup_inputs)
#define B_  4
#define L_  2048
#define H_  8
#define D_  64
#define NS  40          // U_part = u = 40
#define NBH (B_*H_)
#define NQBLK 8         // queries per update-block

// Scratch (no cudaMalloc allowed)
__device__ int   g_idx[L_*NS];
__device__ float g_M[NBH*L_];
__device__ int   g_top[NBH*NS];
__device__ __align__(16) float g_vmean[NBH*D_];

// ---------------- threefry2x32 ----------------
__device__ __forceinline__ uint32_t rotl32(uint32_t x, int r) {
    return (x << r) | (x >> (32 - r));
}
__device__ __forceinline__ void threefry2x32(uint32_t k0, uint32_t k1,
                                             uint32_t c0, uint32_t c1,
                                             uint32_t& o0, uint32_t& o1) {
    uint32_t ks0 = k0, ks1 = k1, ks2 = k0 ^ k1 ^ 0x1BD11BDAu;
    uint32_t x0 = c0 + ks0, x1 = c1 + ks1;
#define TF_RND(R) { x0 += x1; x1 = rotl32(x1, R); x1 ^= x0; }
    TF_RND(13) TF_RND(15) TF_RND(26) TF_RND(6)  x0 += ks1; x1 += ks2 + 1u;
    TF_RND(17) TF_RND(29) TF_RND(16) TF_RND(24) x0 += ks2; x1 += ks0 + 2u;
    TF_RND(13) TF_RND(15) TF_RND(26) TF_RND(6)  x0 += ks0; x1 += ks1 + 3u;
    TF_RND(17) TF_RND(29) TF_RND(16) TF_RND(24) x0 += ks1; x1 += ks2 + 4u;
    TF_RND(13) TF_RND(15) TF_RND(26) TF_RND(6)  x0 += ks2; x1 += ks0 + 5u;
#undef TF_RND
    o0 = x0; o1 = x1;
}

// K0: index_sample = randint(key(42),(2048,40),0,2048) with
// jax_threefry_partitionable=True (modern JAX default):
//   split (fold-like):  k_i = threefry(parent, (0, i)), new key = (out0, out1)
//   random_bits (counter-mode, 32-bit): bits[i] = o0 ^ o1 of threefry(key, (0, i))
//   span=2048 pow2 => multiplier==0 => idx = bits & 2047  (uses k2 = split(key)[1])
__global__ void kernel_idx() {
    int i = blockIdx.x * blockDim.x + threadIdx.x;
    if (i >= L_ * NS) return;
    uint32_t k20, k21;
    threefry2x32(0u, 42u, 0u, 1u, k20, k21);   // k2 = second key of fold-like split
    uint32_t a, b;
    threefry2x32(k20, k21, 0u, (uint32_t)i, a, b);
    g_idx[i] = (int)((a ^ b) & 2047u);
}

// K1: M[b,h,q] = max_s(qk) - mean_s(qk), sampled dots.
// One block per (b,q), warp = h (shares the gathered 2KB key-row across all 8 heads).
__global__ void kernel_M(const float* __restrict__ q, const float* __restrict__ k) {
    int blk = blockIdx.x;              // b*L_ + qi
    int b   = blk >> 11;
    int qi  = blk & (L_ - 1);
    int w   = threadIdx.x >> 5;        // h
    int lane = threadIdx.x & 31;

    __shared__ int sidx[NS];
    if (threadIdx.x < NS) sidx[threadIdx.x] = g_idx[qi * NS + threadIdx.x];
    __syncthreads();

    const float* qr = q + (((size_t)blk) * H_ + w) * D_;
    float q0 = qr[lane], q1 = qr[lane + 32];

    float mx = -INFINITY, sm = 0.0f;
#pragma unroll 4
    for (int s = 0; s < NS; s++) {
        int j = sidx[s];
        const float* kr = k + (((size_t)(b * L_ + j)) * H_ + w) * D_;
        float p = q0 * __ldg(&kr[lane]) + q1 * __ldg(&kr[lane + 32]);
#pragma unroll
        for (int o = 16; o; o >>= 1) p += __shfl_xor_sync(0xffffffffu, p, o);
        mx = fmaxf(mx, p);
        sm += p;
    }
    if (lane == 0) g_M[(b * H_ + w) * L_ + qi] = mx - sm * (1.0f / (float)NS);
}

// K2: top-40 per (b,h), tie-break lower index (matches lax.top_k).
__global__ void kernel_topk() {
    __shared__ float sM[L_];
    __shared__ float rv[256];
    __shared__ int   ri[256];
    int bh = blockIdx.x, t = threadIdx.x;
    for (int j = t; j < L_; j += 256) sM[j] = g_M[bh * L_ + j];
    __syncthreads();
    for (int u = 0; u < NS; u++) {
        float bv = -INFINITY; int bi = L_;
        for (int j = t; j < L_; j += 256) {
            float v = sM[j];
            if (v > bv || (v == bv && j < bi)) { bv = v; bi = j; }
        }
        rv[t] = bv; ri[t] = bi;
        __syncthreads();
        for (int o = 128; o; o >>= 1) {
            if (t < o) {
                float ov = rv[t + o]; int oi = ri[t + o];
                if (ov > rv[t] || (ov == rv[t] && oi < ri[t])) { rv[t] = ov; ri[t] = oi; }
            }
            __syncthreads();
        }
        if (t == 0) { g_top[bh * NS + u] = ri[0]; sM[ri[0]] = -INFINITY; }
        __syncthreads();
    }
}

// K3: V_mean per (b,h,d)
__global__ void kernel_vmean(const float* __restrict__ v) {
    int bh = blockIdx.x; int b = bh >> 3, h = bh & 7;
    int t = threadIdx.x;             // 512
    int d = t & 63, c = t >> 6;      // 8 chunks of 256
    const float* vb = v + ((size_t)b * L_ * H_) * D_ + h * D_ + d;
    float acc = 0.0f;
    for (int l = c * 256; l < c * 256 + 256; l++) acc += vb[(size_t)l * (H_ * D_)];
    __shared__ float red[512];
    red[t] = acc;
    __syncthreads();
    if (t < 64) {
        float s = 0.0f;
#pragma unroll
        for (int cc = 0; cc < 8; cc++) s += red[cc * 64 + t];
        g_vmean[bh * D_ + t] = s * (1.0f / (float)L_);
    }
}

// K3b: broadcast V_mean into the whole output
__global__ void kernel_init(float* __restrict__ out) {
    int i = blockIdx.x * blockDim.x + threadIdx.x;   // float4 units, 1M total
    int d4  = i & 15;
    int row = i >> 4;          // (b*L+l)*H + h
    int h   = row & 7;
    int b   = row >> 14;       // / (L_*H_) = /16384
    float4 vm = ((const float4*)g_vmean)[(b * H_ + h) * 16 + d4];
    ((float4*)out)[i] = vm;
}

// K4: dense attention for the 40 selected queries. Block = (b,h, group of 8 queries).
__global__ void kernel_update(const float* __restrict__ q, const float* __restrict__ k,
                              const float* __restrict__ v, float* __restrict__ out) {
    extern __shared__ float sh[];
    float* s_sc  = sh;                    // NQBLK * L_
    float* s_q   = s_sc + NQBLK * L_;     // NQBLK * D_
    float* s_red = s_q + NQBLK * D_;      // 256

    const int groups = NS / NQBLK;        // 5
    int bx  = blockIdx.x;
    int bh  = bx / groups;
    int grp = bx % groups;
    int b = bh >> 3, h = bh & 7;
    int t = threadIdx.x;                  // 256

    int qidx[NQBLK];
#pragma unroll
    for (int i = 0; i < NQBLK; i++) qidx[i] = g_top[bh * NS + grp * NQBLK + i];

    for (int e = t; e < NQBLK * D_; e += 256) {
        int i = e >> 6, d = e & 63;
        s_q[e] = q[(((size_t)(b * L_ + qidx[i])) * H_ + h) * D_ + d];
    }
    __syncthreads();

    // scores (QK^T * scale)
    const float4* k4 = (const float4*)k;
    const float4* q4 = (const float4*)s_q;
#pragma unroll 1
    for (int rep = 0; rep < L_ / 256; rep++) {
        int j = rep * 256 + t;
        const float4* kr = k4 + (((size_t)(b * L_ + j)) * H_ + h) * (D_ / 4);
        float acc[NQBLK];
#pragma unroll
        for (int i = 0; i < NQBLK; i++) acc[i] = 0.0f;
#pragma unroll
        for (int dv = 0; dv < D_ / 4; dv++) {
            float4 kv = __ldg(&kr[dv]);
#pragma unroll
            for (int i = 0; i < NQBLK; i++) {
                float4 qv = q4[i * (D_ / 4) + dv];
                acc[i] += kv.x * qv.x + kv.y * qv.y + kv.z * qv.z + kv.w * qv.w;
            }
        }
#pragma unroll
        for (int i = 0; i < NQBLK; i++) s_sc[i * L_ + j] = acc[i] * 0.125f;
    }
    __syncthreads();

    // softmax per query row
    for (int i = 0; i < NQBLK; i++) {
        float* sc = s_sc + i * L_;
        float m = -INFINITY;
        for (int j = t; j < L_; j += 256) m = fmaxf(m, sc[j]);
        s_red[t] = m; __syncthreads();
        for (int o = 128; o; o >>= 1) { if (t < o) s_red[t] = fmaxf(s_red[t], s_red[t + o]); __syncthreads(); }
        float gmax = s_red[0];
        __syncthreads();
        float ssum = 0.0f;
        for (int j = t; j < L_; j += 256) { float e = expf(sc[j] - gmax); sc[j] = e; ssum += e; }
        s_red[t] = ssum; __syncthreads();
        for (int o = 128; o; o >>= 1) { if (t < o) s_red[t] += s_red[t + o]; __syncthreads(); }
        float inv = 1.0f / s_red[0];
        __syncthreads();
        for (int j = t; j < L_; j += 256) sc[j] *= inv;
        __syncthreads();
    }

    // update = attn @ V ; thread t -> d = t&63, key-chunk c = t>>6
    int d = t & 63, c = t >> 6;
    float accs[NQBLK];
#pragma unroll
    for (int i = 0; i < NQBLK; i++) accs[i] = 0.0f;
    const float* vb = v + ((size_t)b * L_ * H_) * D_ + h * D_ + d;
    for (int j = c * 512; j < c * 512 + 512; j++) {
        float vv = __ldg(&vb[(size_t)j * (H_ * D_)]);
#pragma unroll
        for (int i = 0; i < NQBLK; i++) accs[i] += s_sc[i * L_ + j] * vv;
    }
    for (int i = 0; i < NQBLK; i++) {
        s_red[t] = accs[i];
        __syncthreads();
        if (t < 64) {
            float tot = s_red[t] + s_red[t + 64] + s_red[t + 128] + s_red[t + 192];
            out[(((size_t)(b * L_ + qidx[i])) * H_ + h) * D_ + t] = tot;
        }
        __syncthreads();
    }
}

extern "C" void kernel_launch(void* const* d_in, const int* in_sizes, int n_in,
                              void* d_out, int out_size) {
    const float* q = (const float*)d_in[0];
    const float* k = (const float*)d_in[1];
    const float* v = (const float*)d_in[2];
    float* out = (float*)d_out;

    static const size_t upd_smem = (size_t)(NQBLK * L_ + NQBLK * D_ + 256) * sizeof(float);
    cudaFuncSetAttribute(kernel_update, cudaFuncAttributeMaxDynamicSharedMemorySize, (int)upd_smem);

    kernel_idx<<<(L_ * NS + 255) / 256, 256>>>();
    kernel_M<<<B_ * L_, 256>>>(q, k);
    kernel_topk<<<NBH, 256>>>();
    kernel_vmean<<<NBH, 512>>>(v);
    kernel_init<<<(B_ * L_ * H_ * D_ / 4) / 256, 256>>>(out);
    kernel_update<<<NBH * (NS / NQBLK), 256, upd_smem>>>(q, k, v, out);
}

// round 3
// speedup vs baseline: 1.5917x; 1.5917x over previous
#include <cuda_runtime.h>
#include <cstdint>

#define B_  4
#define L_  2048
#define H_  8
#define D_  64
#define NS  40
#define NBH (B_*H_)
#define NQBLK 8

__device__ int   g_idx[L_*NS];
__device__ float g_M[NBH*L_];
__device__ int   g_top[NBH*NS];
__device__ __align__(16) float g_vmean[NBH*D_];
__device__ __align__(16) float g_vpart[NBH*8*D_];

// ---------------- threefry2x32 ----------------
__device__ __forceinline__ uint32_t rotl32(uint32_t x, int r) {
    return (x << r) | (x >> (32 - r));
}
__device__ __forceinline__ void threefry2x32(uint32_t k0, uint32_t k1,
                                             uint32_t c0, uint32_t c1,
                                             uint32_t& o0, uint32_t& o1) {
    uint32_t ks0 = k0, ks1 = k1, ks2 = k0 ^ k1 ^ 0x1BD11BDAu;
    uint32_t x0 = c0 + ks0, x1 = c1 + ks1;
#define TF_RND(R) { x0 += x1; x1 = rotl32(x1, R); x1 ^= x0; }
    TF_RND(13) TF_RND(15) TF_RND(26) TF_RND(6)  x0 += ks1; x1 += ks2 + 1u;
    TF_RND(17) TF_RND(29) TF_RND(16) TF_RND(24) x0 += ks2; x1 += ks0 + 2u;
    TF_RND(13) TF_RND(15) TF_RND(26) TF_RND(6)  x0 += ks0; x1 += ks1 + 3u;
    TF_RND(17) TF_RND(29) TF_RND(16) TF_RND(24) x0 += ks1; x1 += ks2 + 4u;
    TF_RND(13) TF_RND(15) TF_RND(26) TF_RND(6)  x0 += ks2; x1 += ks0 + 5u;
#undef TF_RND
    o0 = x0; o1 = x1;
}

// K0: partitionable threefry randint (span=2048 pow2 -> multiplier 0 -> bits & 2047)
__global__ void kernel_idx() {
    int i = blockIdx.x * blockDim.x + threadIdx.x;
    if (i >= L_ * NS) return;
    uint32_t k20, k21;
    threefry2x32(0u, 42u, 0u, 1u, k20, k21);
    uint32_t a, b;
    threefry2x32(k20, k21, 0u, (uint32_t)i, a, b);
    g_idx[i] = (int)((a ^ b) & 2047u);
}

// K1: M = max - mean of sampled dots. Block = (b,q), warp = head.
// 4 samples per warp-pass, 8 lanes per sample, float4 loads, 3-level shfl.
__global__ void kernel_M(const float* __restrict__ q, const float* __restrict__ k) {
    int blk = blockIdx.x;              // b*L_ + qi
    int b   = blk >> 11;
    int qi  = blk & (L_ - 1);
    int w   = threadIdx.x >> 5;        // head
    int lane = threadIdx.x & 31;
    int g = lane >> 3;                 // sample-group 0..3
    int r = lane & 7;                  // d-slot within sample

    __shared__ int sidx[NS];
    if (threadIdx.x < NS) sidx[threadIdx.x] = g_idx[qi * NS + threadIdx.x];
    __syncthreads();

    const float4* q4 = (const float4*)(q + (((size_t)blk) * H_ + w) * D_);
    float4 qa = q4[r], qb = q4[r + 8];

    const float4* kbase = (const float4*)k + ((size_t)b * L_) * (H_ * D_ / 4) + w * (D_ / 4);

    float mx = -INFINITY, sm = 0.0f;
#pragma unroll 2
    for (int s0 = 0; s0 < NS; s0 += 4) {
        int j = sidx[s0 + g];
        const float4* kr = kbase + (size_t)j * (H_ * D_ / 4);
        float4 ka = __ldg(&kr[r]);
        float4 kb = __ldg(&kr[r + 8]);
        float p = ka.x * qa.x + ka.y * qa.y + ka.z * qa.z + ka.w * qa.w
                + kb.x * qb.x + kb.y * qb.y + kb.z * qb.z + kb.w * qb.w;
        p += __shfl_xor_sync(0xffffffffu, p, 4);
        p += __shfl_xor_sync(0xffffffffu, p, 2);
        p += __shfl_xor_sync(0xffffffffu, p, 1);
        mx = fmaxf(mx, p);
        sm += p;
    }
    // combine the 4 sample-groups
    mx = fmaxf(mx, __shfl_xor_sync(0xffffffffu, mx, 8));
    mx = fmaxf(mx, __shfl_xor_sync(0xffffffffu, mx, 16));
    sm += __shfl_xor_sync(0xffffffffu, sm, 8);
    sm += __shfl_xor_sync(0xffffffffu, sm, 16);
    if (lane == 0) g_M[(b * H_ + w) * L_ + qi] = mx - sm * (1.0f / (float)NS);
}

// K2: top-40 per (b,h), register-resident, warp reduce. Tie-break lower index.
__global__ void kernel_topk() {
    int bh = blockIdx.x, t = threadIdx.x;   // 256 threads
    float vals[8];
#pragma unroll
    for (int i = 0; i < 8; i++) vals[i] = g_M[bh * L_ + t * 8 + i];

    __shared__ float wv[8];
    __shared__ int   wi[8];
    __shared__ int   sbi;
    int warp = t >> 5, lane = t & 31;

    for (int u = 0; u < NS; u++) {
        float bv = -INFINITY; int bi = 1 << 30;
#pragma unroll
        for (int i = 0; i < 8; i++) {
            if (vals[i] > bv) { bv = vals[i]; bi = t * 8 + i; }   // ascending -> lowest idx on tie
        }
#pragma unroll
        for (int o = 16; o; o >>= 1) {
            float ov = __shfl_xor_sync(0xffffffffu, bv, o);
            int   oi = __shfl_xor_sync(0xffffffffu, bi, o);
            if (ov > bv || (ov == bv && oi < bi)) { bv = ov; bi = oi; }
        }
        if (lane == 0) { wv[warp] = bv; wi[warp] = bi; }
        __syncthreads();
        if (t == 0) {
            float fb = wv[0]; int fi = wi[0];
#pragma unroll
            for (int wd = 1; wd < 8; wd++) {
                if (wv[wd] > fb || (wv[wd] == fb && wi[wd] < fi)) { fb = wv[wd]; fi = wi[wd]; }
            }
            g_top[bh * NS + u] = fi;
            sbi = fi;
        }
        __syncthreads();
        int fi = sbi;
        if ((fi >> 3) == t) vals[fi & 7] = -INFINITY;
        __syncthreads();
    }
}

// K3a: V_mean partials. Block = (bh, L-chunk of 256). 256 threads.
__global__ void kernel_vmean(const float* __restrict__ v) {
    int bh = blockIdx.x >> 3, c = blockIdx.x & 7;
    int b = bh >> 3, h = bh & 7;
    int t = threadIdx.x;
    int d4 = t & 15, r = t >> 4;       // 16 rows in flight

    const float4* v4 = (const float4*)v;
    size_t base = ((size_t)b * L_) * (H_ * D_ / 4) + h * (D_ / 4) + d4;
    float4 acc = make_float4(0.f, 0.f, 0.f, 0.f);
#pragma unroll 4
    for (int i = 0; i < 16; i++) {
        int l = c * 256 + i * 16 + r;
        float4 x = __ldg(&v4[base + (size_t)l * (H_ * D_ / 4)]);
        acc.x += x.x; acc.y += x.y; acc.z += x.z; acc.w += x.w;
    }
    __shared__ float4 sred[256];
    sred[t] = acc;
    __syncthreads();
    if (t < 16) {
        float4 s = sred[t];
#pragma unroll
        for (int rr = 1; rr < 16; rr++) {
            float4 x = sred[rr * 16 + t];
            s.x += x.x; s.y += x.y; s.z += x.z; s.w += x.w;
        }
        ((float4*)g_vpart)[(bh * 8 + c) * 16 + t] = s;
    }
}

// K3b: reduce partials -> g_vmean
__global__ void kernel_vmean_final() {
    int i = blockIdx.x * blockDim.x + threadIdx.x;   // 2048
    int bh = i >> 6, d = i & 63;
    float s = 0.0f;
#pragma unroll
    for (int c = 0; c < 8; c++) s += g_vpart[(bh * 8 + c) * 64 + d];
    g_vmean[i] = s * (1.0f / (float)L_);
}

// K3c: broadcast V_mean into output
__global__ void kernel_init(float* __restrict__ out) {
    int i = blockIdx.x * blockDim.x + threadIdx.x;   // float4 units, 1M
    int d4  = i & 15;
    int row = i >> 4;
    int h   = row & 7;
    int b   = row >> 14;
    float4 vm = ((const float4*)g_vmean)[(b * H_ + h) * 16 + d4];
    ((float4*)out)[i] = vm;
}

// K4: dense attention for 40 selected queries. 512 threads/block.
__global__ void kernel_update(const float* __restrict__ q, const float* __restrict__ k,
                              const float* __restrict__ v, float* __restrict__ out) {
    extern __shared__ float sh[];
    float* s_sc  = sh;                    // NQBLK * L_
    float* s_q   = s_sc + NQBLK * L_;     // NQBLK * D_
    float* s_red = s_q + NQBLK * D_;      // 512

    const int groups = NS / NQBLK;        // 5
    int bx  = blockIdx.x;
    int bh  = bx / groups;
    int grp = bx % groups;
    int b = bh >> 3, h = bh & 7;
    int t = threadIdx.x;                  // 512

    int qidx[NQBLK];
#pragma unroll
    for (int i = 0; i < NQBLK; i++) qidx[i] = g_top[bh * NS + grp * NQBLK + i];

    for (int e = t; e < NQBLK * D_; e += 512) {
        int i = e >> 6, d = e & 63;
        s_q[e] = q[(((size_t)(b * L_ + qidx[i])) * H_ + h) * D_ + d];
    }
    __syncthreads();

    const float4* k4 = (const float4*)k;
    const float4* q4 = (const float4*)s_q;
#pragma unroll 1
    for (int rep = 0; rep < L_ / 512; rep++) {
        int j = rep * 512 + t;
        const float4* kr = k4 + (((size_t)(b * L_ + j)) * H_ + h) * (D_ / 4);
        float acc[NQBLK];
#pragma unroll
        for (int i = 0; i < NQBLK; i++) acc[i] = 0.0f;
#pragma unroll
        for (int dv = 0; dv < D_ / 4; dv++) {
            float4 kv = __ldg(&kr[dv]);
#pragma unroll
            for (int i = 0; i < NQBLK; i++) {
                float4 qv = q4[i * (D_ / 4) + dv];
                acc[i] += kv.x * qv.x + kv.y * qv.y + kv.z * qv.z + kv.w * qv.w;
            }
        }
#pragma unroll
        for (int i = 0; i < NQBLK; i++) s_sc[i * L_ + j] = acc[i] * 0.125f;
    }
    __syncthreads();

    // softmax per query row
    for (int i = 0; i < NQBLK; i++) {
        float* sc = s_sc + i * L_;
        float m = -INFINITY;
        for (int j = t; j < L_; j += 512) m = fmaxf(m, sc[j]);
        s_red[t] = m; __syncthreads();
        for (int o = 256; o; o >>= 1) { if (t < o) s_red[t] = fmaxf(s_red[t], s_red[t + o]); __syncthreads(); }
        float gmax = s_red[0];
        __syncthreads();
        float ssum = 0.0f;
        for (int j = t; j < L_; j += 512) { float e = __expf(sc[j] - gmax); sc[j] = e; ssum += e; }
        s_red[t] = ssum; __syncthreads();
        for (int o = 256; o; o >>= 1) { if (t < o) s_red[t] += s_red[t + o]; __syncthreads(); }
        float inv = 1.0f / s_red[0];
        __syncthreads();
        for (int j = t; j < L_; j += 512) sc[j] *= inv;
        __syncthreads();
    }

    // update = attn @ V ; d = t&63, key-chunk c = t>>6 (8 chunks of 256)
    int d = t & 63, c = t >> 6;
    float accs[NQBLK];
#pragma unroll
    for (int i = 0; i < NQBLK; i++) accs[i] = 0.0f;
    const float* vb = v + ((size_t)b * L_ * H_) * D_ + h * D_ + d;
    for (int j = c * 256; j < c * 256 + 256; j++) {
        float vv = __ldg(&vb[(size_t)j * (H_ * D_)]);
#pragma unroll
        for (int i = 0; i < NQBLK; i++) accs[i] += s_sc[i * L_ + j] * vv;
    }
    for (int i = 0; i < NQBLK; i++) {
        s_red[t] = accs[i];
        __syncthreads();
        if (t < 64) {
            float tot = 0.0f;
#pragma unroll
            for (int cc = 0; cc < 8; cc++) tot += s_red[cc * 64 + t];
            out[(((size_t)(b * L_ + qidx[i])) * H_ + h) * D_ + t] = tot;
        }
        __syncthreads();
    }
}

extern "C" void kernel_launch(void* const* d_in, const int* in_sizes, int n_in,
                              void* d_out, int out_size) {
    const float* q = (const float*)d_in[0];
    const float* k = (const float*)d_in[1];
    const float* v = (const float*)d_in[2];
    float* out = (float*)d_out;

    static const size_t upd_smem = (size_t)(NQBLK * L_ + NQBLK * D_ + 512) * sizeof(float);
    cudaFuncSetAttribute(kernel_update, cudaFuncAttributeMaxDynamicSharedMemorySize, (int)upd_smem);

    kernel_idx<<<(L_ * NS + 255) / 256, 256>>>();
    kernel_M<<<B_ * L_, 256>>>(q, k);
    kernel_topk<<<NBH, 256>>>();
    kernel_vmean<<<NBH * 8, 256>>>(v);
    kernel_vmean_final<<<8, 256>>>();
    kernel_init<<<(B_ * L_ * H_ * D_ / 4) / 256, 256>>>(out);
    kernel_update<<<NBH * (NS / NQBLK), 512, upd_smem>>>(q, k, v, out);
}